// round 5
// baseline (speedup 1.0000x reference)
#include <cuda_runtime.h>
#include <math.h>

// ---------------------------------------------------------------------------
// Problem constants
// ---------------------------------------------------------------------------
#define N_      4
#define T_      2048
#define C_      1024        // = H*HS = attention dim = model dim
#define MTOT    (N_ * T_)   // 8192 rows for the GEMMs
#define NCHUNK  16
#define CS      (T_ / NCHUNK)   // 128 timesteps per chunk

// ---------------------------------------------------------------------------
// Scratch (allocation-free: __device__ globals)
// ---------------------------------------------------------------------------
__device__ float g_XR[MTOT * C_];   // interpolated input for R
__device__ float g_XK[MTOT * C_];
__device__ float g_XV[MTOT * C_];
__device__ float g_R [MTOT * C_];
__device__ float g_K [MTOT * C_];
__device__ float g_V [MTOT * C_];
__device__ float g_G [MTOT * C_];   // sigmoid(R)*WKV
__device__ float g_SA[N_ * NCHUNK * C_];
__device__ float g_SB[N_ * NCHUNK * C_];

// ---------------------------------------------------------------------------
// Helpers
// ---------------------------------------------------------------------------
__device__ __forceinline__ float clip_wk(float x) {
    return fminf(fmaxf(x, -20.0f), 10.0f);
}

// ---------------------------------------------------------------------------
// 1) Time interpolation: out[t] = eps*x[t-1] + (1-eps)*x[t+1], zero-padded
// ---------------------------------------------------------------------------
__global__ void interp_kernel(const float* __restrict__ x,
                              float er, float omr,
                              float ek, float omk,
                              float ev, float omv)
{
    int idx = blockIdx.x * blockDim.x + threadIdx.x;
    if (idx >= MTOT * C_) return;
    int t = (idx / C_) % T_;
    float prev = (t > 0)      ? x[idx - C_] : 0.0f;   // x[t-1]
    float next = (t < T_ - 1) ? x[idx + C_] : 0.0f;   // x[t+1]
    g_XR[idx] = er * prev + omr * next;
    g_XK[idx] = ek * prev + omk * next;
    g_XV[idx] = ev * prev + omv * next;
}

// ---------------------------------------------------------------------------
// 2) SGEMM (NT): C[m,j] = sum_k A[m,k]*B[j,k] + bias[j]
//    A: [M,K] row-major, B: [Nn,K] row-major (i.e. weight W, so A @ W^T)
//    128x128 block tile, BK=8, 8x8 thread microtile, 256 threads
// ---------------------------------------------------------------------------
#define BM 128
#define BN 128
#define BK 8
#define TM 8
#define TN 8

__global__ __launch_bounds__(256)
void sgemm_nt_bias(const float* __restrict__ A,
                   const float* __restrict__ B,
                   const float* __restrict__ bias,
                   float* __restrict__ Cout,
                   int M, int Nn, int K)
{
    __shared__ float As[BK][BM];
    __shared__ float Bs[BK][BN];

    const int tid = threadIdx.x;
    const int bm  = blockIdx.y * BM;
    const int bn  = blockIdx.x * BN;

    // global load mapping: each thread loads one float4 from A and one from B
    const int lr = tid >> 1;           // 0..127 : row within tile
    const int lk = (tid & 1) * 4;      // 0 or 4 : k offset within BK

    // compute mapping
    const int tx = tid & 15;           // 0..15 -> column group (TN each)
    const int ty = tid >> 4;           // 0..15 -> row group (TM each)

    const float* Aptr = A + (size_t)(bm + lr) * K + lk;
    const float* Bptr = B + (size_t)(bn + lr) * K + lk;

    float acc[TM][TN];
    #pragma unroll
    for (int i = 0; i < TM; i++)
        #pragma unroll
        for (int j = 0; j < TN; j++)
            acc[i][j] = 0.0f;

    for (int k0 = 0; k0 < K; k0 += BK) {
        float4 a4 = *reinterpret_cast<const float4*>(Aptr + k0);
        float4 b4 = *reinterpret_cast<const float4*>(Bptr + k0);
        As[lk + 0][lr] = a4.x;
        As[lk + 1][lr] = a4.y;
        As[lk + 2][lr] = a4.z;
        As[lk + 3][lr] = a4.w;
        Bs[lk + 0][lr] = b4.x;
        Bs[lk + 1][lr] = b4.y;
        Bs[lk + 2][lr] = b4.z;
        Bs[lk + 3][lr] = b4.w;
        __syncthreads();

        #pragma unroll
        for (int kk = 0; kk < BK; kk++) {
            float ra[TM], rb[TN];
            #pragma unroll
            for (int i = 0; i < TM; i++) ra[i] = As[kk][ty * TM + i];
            #pragma unroll
            for (int j = 0; j < TN; j++) rb[j] = Bs[kk][tx * TN + j];
            #pragma unroll
            for (int i = 0; i < TM; i++)
                #pragma unroll
                for (int j = 0; j < TN; j++)
                    acc[i][j] = fmaf(ra[i], rb[j], acc[i][j]);
        }
        __syncthreads();
    }

    // epilogue: bias + store
    #pragma unroll
    for (int i = 0; i < TM; i++) {
        int row = bm + ty * TM + i;
        #pragma unroll
        for (int j = 0; j < TN; j++) {
            int col = bn + tx * TN + j;
            Cout[(size_t)row * Nn + col] = acc[i][j] + bias[col];
        }
    }
}

// ---------------------------------------------------------------------------
// 3) WKV recurrence (chunk-parallel cumsum, 3 passes)
//    e_t  = exp(clip(-w*(T-1-t) + k_t))
//    A_t  = sum_{i<t} e_i v_i + exp(clip(u + k_t)) v_t
//    B_t  = sum_{i<t} e_i     + exp(clip(u + k_t))
//    G_t  = sigmoid(r_t) * A_t / B_t
// ---------------------------------------------------------------------------
__global__ __launch_bounds__(1024)
void wkv_partial(const float* __restrict__ td)
{
    const int c     = threadIdx.x;
    const int chunk = blockIdx.x;
    const int n     = blockIdx.y;
    const float w   = fmaxf(td[c], 0.0f);

    const int t0 = chunk * CS;
    const float* kp = g_K + ((size_t)n * T_ + t0) * C_ + c;
    const float* vp = g_V + ((size_t)n * T_ + t0) * C_ + c;

    float sa = 0.0f, sb = 0.0f;
    #pragma unroll 4
    for (int i = 0; i < CS; i++) {
        int t   = t0 + i;
        float k = kp[(size_t)i * C_];
        float v = vp[(size_t)i * C_];
        float e = expf(clip_wk(fmaf(-w, (float)(T_ - 1 - t), k)));
        sa = fmaf(e, v, sa);
        sb += e;
    }
    size_t o = ((size_t)n * NCHUNK + chunk) * C_ + c;
    g_SA[o] = sa;
    g_SB[o] = sb;
}

__global__ void wkv_scan()
{
    int idx = blockIdx.x * blockDim.x + threadIdx.x;   // over N_*C_
    if (idx >= N_ * C_) return;
    int n = idx / C_;
    int c = idx % C_;
    float ra = 0.0f, rb = 0.0f;
    for (int ch = 0; ch < NCHUNK; ch++) {
        size_t o = ((size_t)n * NCHUNK + ch) * C_ + c;
        float ta = g_SA[o], tb = g_SB[o];
        g_SA[o] = ra;                 // exclusive prefix
        g_SB[o] = rb;
        ra += ta;
        rb += tb;
    }
}

__global__ __launch_bounds__(1024)
void wkv_final(const float* __restrict__ td, const float* __restrict__ U)
{
    const int c     = threadIdx.x;
    const int chunk = blockIdx.x;
    const int n     = blockIdx.y;
    const float w   = fmaxf(td[c], 0.0f);
    const float u   = U[c];

    size_t so = ((size_t)n * NCHUNK + chunk) * C_ + c;
    float aa = g_SA[so];
    float bb = g_SB[so];

    const int t0 = chunk * CS;
    const size_t base = ((size_t)n * T_ + t0) * C_ + c;
    const float* rp = g_R + base;
    const float* kp = g_K + base;
    const float* vp = g_V + base;
    float*       gp = g_G + base;

    #pragma unroll 4
    for (int i = 0; i < CS; i++) {
        int t   = t0 + i;
        float r = rp[(size_t)i * C_];
        float k = kp[(size_t)i * C_];
        float v = vp[(size_t)i * C_];

        float eu   = expf(clip_wk(u + k));
        float Aval = fmaf(eu, v, aa);
        float Bval = bb + eu;
        float wkv  = Aval / Bval;
        float sig  = 1.0f / (1.0f + expf(-r));
        gp[(size_t)i * C_] = sig * wkv;

        float e = expf(clip_wk(fmaf(-w, (float)(T_ - 1 - t), k)));
        aa = fmaf(e, v, aa);
        bb += e;
    }
}

// ---------------------------------------------------------------------------
// Launch
// ---------------------------------------------------------------------------
extern "C" void kernel_launch(void* const* d_in, const int* in_sizes, int n_in,
                              void* d_out, int out_size)
{
    const float* x   = (const float*)d_in[0];
    const float* Wr  = (const float*)d_in[1];
    const float* br  = (const float*)d_in[2];
    const float* Wk  = (const float*)d_in[3];
    const float* bk  = (const float*)d_in[4];
    const float* Wv  = (const float*)d_in[5];
    const float* bv  = (const float*)d_in[6];
    const float* Wo  = (const float*)d_in[7];
    const float* bo  = (const float*)d_in[8];
    const float* td  = (const float*)d_in[9];
    const float* U   = (const float*)d_in[10];
    float*       out = (float*)d_out;

    // eps constants, computed in double then rounded (matches jax weak-typing)
    const double EPSd  = exp(-1.0 / 12.0);
    const float  er = (float)(EPSd / 2.0);
    const float  omr = (float)(1.0 - EPSd / 2.0);
    const float  ek = (float)(EPSd + 0.3 * 1.0 / 11.0);
    const float  omk = (float)(1.0 - (EPSd + 0.3 * 1.0 / 11.0));
    const float  ev = (float)EPSd;
    const float  omv = (float)(1.0 - EPSd);

    float *XR, *XK, *XV, *Rb, *Kb, *Vb, *Gb;
    cudaGetSymbolAddress((void**)&XR, g_XR);
    cudaGetSymbolAddress((void**)&XK, g_XK);
    cudaGetSymbolAddress((void**)&XV, g_XV);
    cudaGetSymbolAddress((void**)&Rb, g_R);
    cudaGetSymbolAddress((void**)&Kb, g_K);
    cudaGetSymbolAddress((void**)&Vb, g_V);
    cudaGetSymbolAddress((void**)&Gb, g_G);

    // 1) time interpolation
    {
        int total = MTOT * C_;
        interp_kernel<<<(total + 255) / 256, 256>>>(x, er, omr, ek, omk, ev, omv);
    }

    // 2) R/K/V projections
    dim3 ggrid(C_ / BN, MTOT / BM);   // (8, 64)
    sgemm_nt_bias<<<ggrid, 256>>>(XR, Wr, br, Rb, MTOT, C_, C_);
    sgemm_nt_bias<<<ggrid, 256>>>(XK, Wk, bk, Kb, MTOT, C_, C_);
    sgemm_nt_bias<<<ggrid, 256>>>(XV, Wv, bv, Vb, MTOT, C_, C_);

    // 3) WKV (chunk-parallel cumsum)
    dim3 wgrid(NCHUNK, N_);
    wkv_partial<<<wgrid, C_>>>(td);
    wkv_scan<<<(N_ * C_ + 255) / 256, 256>>>();
    wkv_final<<<wgrid, C_>>>(td, U);

    // 4) output projection
    sgemm_nt_bias<<<ggrid, 256>>>(Gb, Wo, bo, out, MTOT, C_, C_);
}

// round 6
// speedup vs baseline: 2.0919x; 2.0919x over previous
#include <cuda_runtime.h>
#include <math.h>
#include <stdint.h>

// ---------------------------------------------------------------------------
// Problem constants
// ---------------------------------------------------------------------------
#define N_      4
#define T_      2048
#define C_      1024        // = H*HS = attention dim = model dim
#define MTOT    (N_ * T_)   // 8192 rows for the GEMMs
#define NCHUNK  16
#define CS      (T_ / NCHUNK)   // 128 timesteps per chunk

// ---------------------------------------------------------------------------
// Scratch (allocation-free: __device__ globals)
// ---------------------------------------------------------------------------
__device__ float g_R [MTOT * C_];
__device__ float g_K [MTOT * C_];
__device__ float g_V [MTOT * C_];
__device__ float g_G [MTOT * C_];   // sigmoid(R)*WKV
__device__ float g_SA[N_ * NCHUNK * C_];
__device__ float g_SB[N_ * NCHUNK * C_];

// ---------------------------------------------------------------------------
// Helpers
// ---------------------------------------------------------------------------
__device__ __forceinline__ float clip_wk(float x) {
    return fminf(fmaxf(x, -20.0f), 10.0f);
}

__device__ __forceinline__ uint32_t f2tf32(float f) {
    uint32_t u;
    asm("cvt.rna.tf32.f32 %0, %1;" : "=r"(u) : "f"(f));
    return u;
}

__device__ __forceinline__ void mma_tf32(float* d, const uint32_t* a, const uint32_t* b) {
    asm volatile(
        "mma.sync.aligned.m16n8k8.row.col.f32.tf32.tf32.f32 "
        "{%0,%1,%2,%3}, {%4,%5,%6,%7}, {%8,%9}, {%0,%1,%2,%3};\n"
        : "+f"(d[0]), "+f"(d[1]), "+f"(d[2]), "+f"(d[3])
        : "r"(a[0]), "r"(a[1]), "r"(a[2]), "r"(a[3]), "r"(b[0]), "r"(b[1]));
}

// ---------------------------------------------------------------------------
// TF32 tensor-core GEMM (NT): C[m,j] = sum_k A[m,k]*W[j,k] + bias[j]
//   Optionally fuses the time interpolation into the A-tile load:
//   A[m,k] = e0 * x[m-1,k] + e1 * x[m+1,k]  (zero at t-boundaries)
//
//   128x128 block tile, BK=32, 8 warps, each warp 64x32 (4x4 m16n8k8 frags).
// ---------------------------------------------------------------------------
#define BM 128
#define BN 128
#define BK 32
#define LDSS 36   // BK + 4 pad: fragment LDS bank = (4*g + t) mod 32, conflict-free

__global__ __launch_bounds__(256, 2)
void gemm_tf32(const float* __restrict__ A,
               const float* __restrict__ W,
               const float* __restrict__ bias,
               float* __restrict__ Cout,
               int do_interp, float e0, float e1)
{
    __shared__ uint32_t As[BM][LDSS];
    __shared__ uint32_t Bs[BN][LDSS];

    const int K  = C_;
    const int Nn = C_;

    const int tid    = threadIdx.x;
    const int bm     = blockIdx.y * BM;
    const int bn     = blockIdx.x * BN;
    const int warpId = tid >> 5;
    const int lane   = tid & 31;
    const int g      = lane >> 2;     // 0..7
    const int t4     = lane & 3;      // 0..3
    const int wr     = (warpId >> 2) * 64;  // warp row offset within tile
    const int wc     = (warpId & 3) * 32;   // warp col offset within tile

    // global->smem mapping: each thread loads float4 at (lrow + 32i, lcol)
    const int lrow = tid >> 3;        // 0..31
    const int lcol = (tid & 7) * 4;   // 0,4,...,28

    float acc[4][4][4];
    #pragma unroll
    for (int i = 0; i < 4; i++)
        #pragma unroll
        for (int j = 0; j < 4; j++)
            #pragma unroll
            for (int q = 0; q < 4; q++)
                acc[i][j][q] = 0.0f;

    for (int k0 = 0; k0 < K; k0 += BK) {
        // ---- load A tile (optionally fused interp) ----
        #pragma unroll
        for (int i = 0; i < 4; i++) {
            const int r = lrow + i * 32;
            const int m = bm + r;
            float4 v;
            if (do_interp) {
                const int tt = m & (T_ - 1);
                float4 p = make_float4(0.f, 0.f, 0.f, 0.f);
                float4 nx = make_float4(0.f, 0.f, 0.f, 0.f);
                if (tt > 0)
                    p = *reinterpret_cast<const float4*>(A + (size_t)(m - 1) * K + k0 + lcol);
                if (tt < T_ - 1)
                    nx = *reinterpret_cast<const float4*>(A + (size_t)(m + 1) * K + k0 + lcol);
                v.x = e0 * p.x + e1 * nx.x;
                v.y = e0 * p.y + e1 * nx.y;
                v.z = e0 * p.z + e1 * nx.z;
                v.w = e0 * p.w + e1 * nx.w;
            } else {
                v = *reinterpret_cast<const float4*>(A + (size_t)m * K + k0 + lcol);
            }
            As[r][lcol + 0] = f2tf32(v.x);
            As[r][lcol + 1] = f2tf32(v.y);
            As[r][lcol + 2] = f2tf32(v.z);
            As[r][lcol + 3] = f2tf32(v.w);
        }
        // ---- load W tile ----
        #pragma unroll
        for (int i = 0; i < 4; i++) {
            const int r = lrow + i * 32;
            float4 v = *reinterpret_cast<const float4*>(W + (size_t)(bn + r) * K + k0 + lcol);
            Bs[r][lcol + 0] = f2tf32(v.x);
            Bs[r][lcol + 1] = f2tf32(v.y);
            Bs[r][lcol + 2] = f2tf32(v.z);
            Bs[r][lcol + 3] = f2tf32(v.w);
        }
        __syncthreads();

        // ---- 4 k-steps of 8 ----
        #pragma unroll
        for (int kk = 0; kk < 4; kk++) {
            const int kb = kk * 8;
            uint32_t afr[4][4];
            uint32_t bfr[4][2];
            #pragma unroll
            for (int mt = 0; mt < 4; mt++) {
                const int r0 = wr + mt * 16;
                afr[mt][0] = As[r0 + g    ][kb + t4    ];
                afr[mt][1] = As[r0 + g + 8][kb + t4    ];
                afr[mt][2] = As[r0 + g    ][kb + t4 + 4];
                afr[mt][3] = As[r0 + g + 8][kb + t4 + 4];
            }
            #pragma unroll
            for (int nt = 0; nt < 4; nt++) {
                const int c0 = wc + nt * 8;
                bfr[nt][0] = Bs[c0 + g][kb + t4    ];
                bfr[nt][1] = Bs[c0 + g][kb + t4 + 4];
            }
            #pragma unroll
            for (int mt = 0; mt < 4; mt++)
                #pragma unroll
                for (int nt = 0; nt < 4; nt++)
                    mma_tf32(acc[mt][nt], afr[mt], bfr[nt]);
        }
        __syncthreads();
    }

    // ---- epilogue: bias + store (float2 per fragment half) ----
    #pragma unroll
    for (int mt = 0; mt < 4; mt++) {
        const int row = bm + wr + mt * 16 + g;
        #pragma unroll
        for (int nt = 0; nt < 4; nt++) {
            const int col = bn + wc + nt * 8 + t4 * 2;
            const float b0 = bias[col];
            const float b1 = bias[col + 1];
            float2 v0 = make_float2(acc[mt][nt][0] + b0, acc[mt][nt][1] + b1);
            float2 v1 = make_float2(acc[mt][nt][2] + b0, acc[mt][nt][3] + b1);
            *reinterpret_cast<float2*>(Cout + (size_t)row * Nn + col) = v0;
            *reinterpret_cast<float2*>(Cout + (size_t)(row + 8) * Nn + col) = v1;
        }
    }
}

// ---------------------------------------------------------------------------
// WKV recurrence (chunk-parallel cumsum, 3 passes)
// ---------------------------------------------------------------------------
__global__ __launch_bounds__(1024)
void wkv_partial(const float* __restrict__ td)
{
    const int c     = threadIdx.x;
    const int chunk = blockIdx.x;
    const int n     = blockIdx.y;
    const float w   = fmaxf(td[c], 0.0f);

    const int t0 = chunk * CS;
    const float* kp = g_K + ((size_t)n * T_ + t0) * C_ + c;
    const float* vp = g_V + ((size_t)n * T_ + t0) * C_ + c;

    float sa = 0.0f, sb = 0.0f;
    #pragma unroll 4
    for (int i = 0; i < CS; i++) {
        int t   = t0 + i;
        float k = kp[(size_t)i * C_];
        float v = vp[(size_t)i * C_];
        float e = __expf(clip_wk(fmaf(-w, (float)(T_ - 1 - t), k)));
        sa = fmaf(e, v, sa);
        sb += e;
    }
    size_t o = ((size_t)n * NCHUNK + chunk) * C_ + c;
    g_SA[o] = sa;
    g_SB[o] = sb;
}

__global__ void wkv_scan()
{
    int idx = blockIdx.x * blockDim.x + threadIdx.x;   // over N_*C_
    if (idx >= N_ * C_) return;
    int n = idx / C_;
    int c = idx % C_;
    float ra = 0.0f, rb = 0.0f;
    for (int ch = 0; ch < NCHUNK; ch++) {
        size_t o = ((size_t)n * NCHUNK + ch) * C_ + c;
        float ta = g_SA[o], tb = g_SB[o];
        g_SA[o] = ra;                 // exclusive prefix
        g_SB[o] = rb;
        ra += ta;
        rb += tb;
    }
}

__global__ __launch_bounds__(1024)
void wkv_final(const float* __restrict__ td, const float* __restrict__ U)
{
    const int c     = threadIdx.x;
    const int chunk = blockIdx.x;
    const int n     = blockIdx.y;
    const float w   = fmaxf(td[c], 0.0f);
    const float u   = U[c];

    size_t so = ((size_t)n * NCHUNK + chunk) * C_ + c;
    float aa = g_SA[so];
    float bb = g_SB[so];

    const int t0 = chunk * CS;
    const size_t base = ((size_t)n * T_ + t0) * C_ + c;
    const float* rp = g_R + base;
    const float* kp = g_K + base;
    const float* vp = g_V + base;
    float*       gp = g_G + base;

    #pragma unroll 4
    for (int i = 0; i < CS; i++) {
        int t   = t0 + i;
        float r = rp[(size_t)i * C_];
        float k = kp[(size_t)i * C_];
        float v = vp[(size_t)i * C_];

        float eu   = __expf(clip_wk(u + k));
        float Aval = fmaf(eu, v, aa);
        float Bval = bb + eu;
        float wkv  = Aval / Bval;
        float sig  = 1.0f / (1.0f + __expf(-r));
        gp[(size_t)i * C_] = sig * wkv;

        float e = __expf(clip_wk(fmaf(-w, (float)(T_ - 1 - t), k)));
        aa = fmaf(e, v, aa);
        bb += e;
    }
}

// ---------------------------------------------------------------------------
// Launch
// ---------------------------------------------------------------------------
extern "C" void kernel_launch(void* const* d_in, const int* in_sizes, int n_in,
                              void* d_out, int out_size)
{
    const float* x   = (const float*)d_in[0];
    const float* Wr  = (const float*)d_in[1];
    const float* br  = (const float*)d_in[2];
    const float* Wk  = (const float*)d_in[3];
    const float* bk  = (const float*)d_in[4];
    const float* Wv  = (const float*)d_in[5];
    const float* bv  = (const float*)d_in[6];
    const float* Wo  = (const float*)d_in[7];
    const float* bo  = (const float*)d_in[8];
    const float* td  = (const float*)d_in[9];
    const float* U   = (const float*)d_in[10];
    float*       out = (float*)d_out;

    // eps constants, computed in double then rounded
    const double EPSd = exp(-1.0 / 12.0);
    const float  er = (float)(EPSd / 2.0);
    const float  omr = (float)(1.0 - EPSd / 2.0);
    const float  ek = (float)(EPSd + 0.3 * 1.0 / 11.0);
    const float  omk = (float)(1.0 - (EPSd + 0.3 * 1.0 / 11.0));
    const float  ev = (float)EPSd;
    const float  omv = (float)(1.0 - EPSd);

    float *Rb, *Kb, *Vb, *Gb;
    cudaGetSymbolAddress((void**)&Rb, g_R);
    cudaGetSymbolAddress((void**)&Kb, g_K);
    cudaGetSymbolAddress((void**)&Vb, g_V);
    cudaGetSymbolAddress((void**)&Gb, g_G);

    dim3 ggrid(C_ / BN, MTOT / BM);   // (8, 64)

    // R/K/V projections with fused time-interp
    gemm_tf32<<<ggrid, 256>>>(x, Wr, br, Rb, 1, er, omr);
    gemm_tf32<<<ggrid, 256>>>(x, Wk, bk, Kb, 1, ek, omk);
    gemm_tf32<<<ggrid, 256>>>(x, Wv, bv, Vb, 1, ev, omv);

    // WKV (chunk-parallel cumsum)
    dim3 wgrid(NCHUNK, N_);
    wkv_partial<<<wgrid, C_>>>(td);
    wkv_scan<<<(N_ * C_ + 255) / 256, 256>>>();
    wkv_final<<<wgrid, C_>>>(td, U);

    // output projection (no interp)
    gemm_tf32<<<ggrid, 256>>>(Gb, Wo, bo, out, 0, 0.0f, 0.0f);
}

// round 7
// speedup vs baseline: 3.7528x; 1.7940x over previous
#include <cuda_runtime.h>
#include <math.h>
#include <stdint.h>

// ---------------------------------------------------------------------------
// Problem constants
// ---------------------------------------------------------------------------
#define N_      4
#define T_      2048
#define C_      1024        // = H*HS = attention dim = model dim
#define MTOT    (N_ * T_)   // 8192 rows for the GEMMs
#define NCHUNK  64
#define CS      (T_ / NCHUNK)   // 32 timesteps per chunk

// ---------------------------------------------------------------------------
// Scratch (allocation-free: __device__ globals)
// ---------------------------------------------------------------------------
__device__ float g_XR[MTOT * C_];   // tf32-rounded interpolated inputs
__device__ float g_XK[MTOT * C_];
__device__ float g_XV[MTOT * C_];
__device__ float g_R [MTOT * C_];
__device__ float g_K [MTOT * C_];
__device__ float g_V [MTOT * C_];
__device__ float g_G [MTOT * C_];   // tf32-rounded sigmoid(R)*WKV
__device__ float g_Wc[4 * C_ * C_]; // tf32-rounded Wr|Wk|Wv|Wo
__device__ float g_SA[N_ * NCHUNK * C_];
__device__ float g_SB[N_ * NCHUNK * C_];

// ---------------------------------------------------------------------------
// Helpers
// ---------------------------------------------------------------------------
__device__ __forceinline__ float clip_wk(float x) {
    return fminf(fmaxf(x, -20.0f), 10.0f);
}

__device__ __forceinline__ float f2tf32f(float f) {
    uint32_t u;
    asm("cvt.rna.tf32.f32 %0, %1;" : "=r"(u) : "f"(f));
    return __uint_as_float(u);
}

__device__ __forceinline__ void mma_tf32(float* d, const uint32_t* a, const uint32_t* b) {
    asm volatile(
        "mma.sync.aligned.m16n8k8.row.col.f32.tf32.tf32.f32 "
        "{%0,%1,%2,%3}, {%4,%5,%6,%7}, {%8,%9}, {%0,%1,%2,%3};\n"
        : "+f"(d[0]), "+f"(d[1]), "+f"(d[2]), "+f"(d[3])
        : "r"(a[0]), "r"(a[1]), "r"(a[2]), "r"(a[3]), "r"(b[0]), "r"(b[1]));
}

__device__ __forceinline__ void cp16(float* smem_dst, const float* gsrc) {
    uint32_t s = (uint32_t)__cvta_generic_to_shared(smem_dst);
    asm volatile("cp.async.cg.shared.global [%0], [%1], 16;\n" :: "r"(s), "l"(gsrc));
}
__device__ __forceinline__ void cp_commit() {
    asm volatile("cp.async.commit_group;\n");
}
__device__ __forceinline__ void cp_wait1() {
    asm volatile("cp.async.wait_group 1;\n");
}
__device__ __forceinline__ void cp_wait0() {
    asm volatile("cp.async.wait_group 0;\n");
}

// ---------------------------------------------------------------------------
// Prep 1: time interpolation + tf32 rounding (float4)
// ---------------------------------------------------------------------------
__global__ void interp_prep(const float* __restrict__ x,
                            float er, float omr,
                            float ek, float omk,
                            float ev, float omv)
{
    int idx4 = blockIdx.x * blockDim.x + threadIdx.x;
    if (idx4 >= MTOT * C_ / 4) return;
    size_t base = (size_t)idx4 * 4;
    int t = (int)((base / C_) % T_);

    float4 p  = make_float4(0.f, 0.f, 0.f, 0.f);
    float4 nx = make_float4(0.f, 0.f, 0.f, 0.f);
    if (t > 0)      p  = *reinterpret_cast<const float4*>(x + base - C_);
    if (t < T_ - 1) nx = *reinterpret_cast<const float4*>(x + base + C_);

    float4 r, k, v;
    r.x = f2tf32f(er * p.x + omr * nx.x);  r.y = f2tf32f(er * p.y + omr * nx.y);
    r.z = f2tf32f(er * p.z + omr * nx.z);  r.w = f2tf32f(er * p.w + omr * nx.w);
    k.x = f2tf32f(ek * p.x + omk * nx.x);  k.y = f2tf32f(ek * p.y + omk * nx.y);
    k.z = f2tf32f(ek * p.z + omk * nx.z);  k.w = f2tf32f(ek * p.w + omk * nx.w);
    v.x = f2tf32f(ev * p.x + omv * nx.x);  v.y = f2tf32f(ev * p.y + omv * nx.y);
    v.z = f2tf32f(ev * p.z + omv * nx.z);  v.w = f2tf32f(ev * p.w + omv * nx.w);

    *reinterpret_cast<float4*>(g_XR + base) = r;
    *reinterpret_cast<float4*>(g_XK + base) = k;
    *reinterpret_cast<float4*>(g_XV + base) = v;
}

// ---------------------------------------------------------------------------
// Prep 2: round weights to tf32.  blockIdx.y selects which weight.
// ---------------------------------------------------------------------------
__global__ void weight_prep(const float* __restrict__ w0, const float* __restrict__ w1,
                            const float* __restrict__ w2, const float* __restrict__ w3)
{
    int idx4 = blockIdx.x * blockDim.x + threadIdx.x;
    if (idx4 >= C_ * C_ / 4) return;
    const float* src = (blockIdx.y == 0) ? w0 : (blockIdx.y == 1) ? w1
                     : (blockIdx.y == 2) ? w2 : w3;
    size_t base = (size_t)idx4 * 4;
    float4 v = *reinterpret_cast<const float4*>(src + base);
    v.x = f2tf32f(v.x); v.y = f2tf32f(v.y); v.z = f2tf32f(v.z); v.w = f2tf32f(v.w);
    *reinterpret_cast<float4*>(g_Wc + (size_t)blockIdx.y * C_ * C_ + base) = v;
}

// ---------------------------------------------------------------------------
// TF32 tensor-core GEMM (NT), cp.async 2-stage pipeline.
//   C[m,j] = sum_k A[m,k]*W[j,k] + bias[j]
//   A, W already tf32-rounded.  128x128x32 tile, 8 warps of 64x32.
// ---------------------------------------------------------------------------
#define BM 128
#define BN 128
#define BK 32
#define LDSS 36                  // 36 floats = 144B row stride: 16B aligned, conflict-free
#define STAGE_SZ (128 * LDSS)    // floats per array per stage

__global__ __launch_bounds__(256, 2)
void gemm_tf32(const float* __restrict__ A,
               const float* __restrict__ W,
               const float* __restrict__ bias,
               float* __restrict__ Cout)
{
    extern __shared__ __align__(16) float sm[];
    float* As = sm;                    // [2][128][LDSS]
    float* Bs = sm + 2 * STAGE_SZ;     // [2][128][LDSS]

    const int K  = C_;
    const int Nn = C_;

    const int tid    = threadIdx.x;
    const int bm     = blockIdx.y * BM;
    const int bn     = blockIdx.x * BN;
    const int warpId = tid >> 5;
    const int lane   = tid & 31;
    const int g      = lane >> 2;           // 0..7
    const int t4     = lane & 3;            // 0..3
    const int wr     = (warpId >> 2) * 64;  // warp row offset
    const int wc     = (warpId & 3) * 32;   // warp col offset

    const int lrow = tid >> 3;              // 0..31
    const int lcol = (tid & 7) * 4;         // 0,4,...,28

    const float* Abase = A + (size_t)(bm + lrow) * K + lcol;
    const float* Bbase = W + (size_t)(bn + lrow) * K + lcol;
    float* Asd = As + lrow * LDSS + lcol;
    float* Bsd = Bs + lrow * LDSS + lcol;

    float acc[4][4][4];
    #pragma unroll
    for (int i = 0; i < 4; i++)
        #pragma unroll
        for (int j = 0; j < 4; j++)
            #pragma unroll
            for (int q = 0; q < 4; q++)
                acc[i][j][q] = 0.0f;

    const int NKT = K / BK;   // 32

    // prologue: stage 0
    {
        #pragma unroll
        for (int i = 0; i < 4; i++) {
            cp16(Asd + i * 32 * LDSS, Abase + i * 32 * (size_t)K);
            cp16(Bsd + i * 32 * LDSS, Bbase + i * 32 * (size_t)K);
        }
        cp_commit();
    }

    for (int kt = 0; kt < NKT; kt++) {
        const int cur = kt & 1;
        if (kt + 1 < NKT) {
            const int nst = cur ^ 1;
            const size_t ko = (size_t)(kt + 1) * BK;
            #pragma unroll
            for (int i = 0; i < 4; i++) {
                cp16(Asd + nst * STAGE_SZ + i * 32 * LDSS, Abase + ko + i * 32 * (size_t)K);
                cp16(Bsd + nst * STAGE_SZ + i * 32 * LDSS, Bbase + ko + i * 32 * (size_t)K);
            }
            cp_commit();
            cp_wait1();
        } else {
            cp_wait0();
        }
        __syncthreads();

        const float* Ab = As + cur * STAGE_SZ;
        const float* Bb = Bs + cur * STAGE_SZ;

        #pragma unroll
        for (int kk = 0; kk < 4; kk++) {
            const int kb = kk * 8;
            uint32_t afr[4][4];
            uint32_t bfr[4][2];
            #pragma unroll
            for (int mt = 0; mt < 4; mt++) {
                const int r0 = wr + mt * 16;
                afr[mt][0] = __float_as_uint(Ab[(r0 + g    ) * LDSS + kb + t4    ]);
                afr[mt][1] = __float_as_uint(Ab[(r0 + g + 8) * LDSS + kb + t4    ]);
                afr[mt][2] = __float_as_uint(Ab[(r0 + g    ) * LDSS + kb + t4 + 4]);
                afr[mt][3] = __float_as_uint(Ab[(r0 + g + 8) * LDSS + kb + t4 + 4]);
            }
            #pragma unroll
            for (int nt = 0; nt < 4; nt++) {
                const int c0 = wc + nt * 8;
                bfr[nt][0] = __float_as_uint(Bb[(c0 + g) * LDSS + kb + t4    ]);
                bfr[nt][1] = __float_as_uint(Bb[(c0 + g) * LDSS + kb + t4 + 4]);
            }
            #pragma unroll
            for (int mt = 0; mt < 4; mt++)
                #pragma unroll
                for (int nt = 0; nt < 4; nt++)
                    mma_tf32(acc[mt][nt], afr[mt], bfr[nt]);
        }
        __syncthreads();
    }

    // epilogue: bias + store
    #pragma unroll
    for (int mt = 0; mt < 4; mt++) {
        const int row = bm + wr + mt * 16 + g;
        #pragma unroll
        for (int nt = 0; nt < 4; nt++) {
            const int col = bn + wc + nt * 8 + t4 * 2;
            const float b0 = bias[col];
            const float b1 = bias[col + 1];
            float2 v0 = make_float2(acc[mt][nt][0] + b0, acc[mt][nt][1] + b1);
            float2 v1 = make_float2(acc[mt][nt][2] + b0, acc[mt][nt][3] + b1);
            *reinterpret_cast<float2*>(Cout + (size_t)row * Nn + col) = v0;
            *reinterpret_cast<float2*>(Cout + (size_t)(row + 8) * Nn + col) = v1;
        }
    }
}

// ---------------------------------------------------------------------------
// WKV recurrence (chunk-parallel cumsum, 3 passes).  256 threads, 4 ch/thread.
// ---------------------------------------------------------------------------
__global__ __launch_bounds__(256)
void wkv_partial(const float* __restrict__ td)
{
    const int c4    = threadIdx.x * 4;
    const int chunk = blockIdx.x;
    const int n     = blockIdx.y;

    float4 wv = *reinterpret_cast<const float4*>(td + c4);
    wv.x = fmaxf(wv.x, 0.f); wv.y = fmaxf(wv.y, 0.f);
    wv.z = fmaxf(wv.z, 0.f); wv.w = fmaxf(wv.w, 0.f);

    const int t0 = chunk * CS;
    const size_t base = ((size_t)n * T_ + t0) * C_ + c4;

    float4 sa = make_float4(0.f, 0.f, 0.f, 0.f);
    float4 sb = make_float4(0.f, 0.f, 0.f, 0.f);

    #pragma unroll 4
    for (int i = 0; i < CS; i++) {
        const float tr = (float)(T_ - 1 - (t0 + i));
        float4 k = *reinterpret_cast<const float4*>(g_K + base + (size_t)i * C_);
        float4 v = *reinterpret_cast<const float4*>(g_V + base + (size_t)i * C_);
        float ex = __expf(clip_wk(fmaf(-wv.x, tr, k.x)));
        float ey = __expf(clip_wk(fmaf(-wv.y, tr, k.y)));
        float ez = __expf(clip_wk(fmaf(-wv.z, tr, k.z)));
        float ew = __expf(clip_wk(fmaf(-wv.w, tr, k.w)));
        sa.x = fmaf(ex, v.x, sa.x); sb.x += ex;
        sa.y = fmaf(ey, v.y, sa.y); sb.y += ey;
        sa.z = fmaf(ez, v.z, sa.z); sb.z += ez;
        sa.w = fmaf(ew, v.w, sa.w); sb.w += ew;
    }
    size_t o = ((size_t)n * NCHUNK + chunk) * C_ + c4;
    *reinterpret_cast<float4*>(g_SA + o) = sa;
    *reinterpret_cast<float4*>(g_SB + o) = sb;
}

__global__ void wkv_scan()
{
    int idx = blockIdx.x * blockDim.x + threadIdx.x;   // over N_*C_
    if (idx >= N_ * C_) return;
    int n = idx / C_;
    int c = idx % C_;
    float ra = 0.0f, rb = 0.0f;
    for (int ch = 0; ch < NCHUNK; ch++) {
        size_t o = ((size_t)n * NCHUNK + ch) * C_ + c;
        float ta = g_SA[o], tb = g_SB[o];
        g_SA[o] = ra;                 // exclusive prefix
        g_SB[o] = rb;
        ra += ta;
        rb += tb;
    }
}

__global__ __launch_bounds__(256)
void wkv_final(const float* __restrict__ td, const float* __restrict__ U)
{
    const int c4    = threadIdx.x * 4;
    const int chunk = blockIdx.x;
    const int n     = blockIdx.y;

    float4 wv = *reinterpret_cast<const float4*>(td + c4);
    wv.x = fmaxf(wv.x, 0.f); wv.y = fmaxf(wv.y, 0.f);
    wv.z = fmaxf(wv.z, 0.f); wv.w = fmaxf(wv.w, 0.f);
    float4 uv = *reinterpret_cast<const float4*>(U + c4);

    size_t so = ((size_t)n * NCHUNK + chunk) * C_ + c4;
    float4 aa = *reinterpret_cast<const float4*>(g_SA + so);
    float4 bb = *reinterpret_cast<const float4*>(g_SB + so);

    const int t0 = chunk * CS;
    const size_t base = ((size_t)n * T_ + t0) * C_ + c4;

    #pragma unroll 2
    for (int i = 0; i < CS; i++) {
        const float tr = (float)(T_ - 1 - (t0 + i));
        float4 r = *reinterpret_cast<const float4*>(g_R + base + (size_t)i * C_);
        float4 k = *reinterpret_cast<const float4*>(g_K + base + (size_t)i * C_);
        float4 v = *reinterpret_cast<const float4*>(g_V + base + (size_t)i * C_);

        float4 gv;
        {
            float eu  = __expf(clip_wk(uv.x + k.x));
            float wkv = fmaf(eu, v.x, aa.x) / (bb.x + eu);
            gv.x = f2tf32f(wkv / (1.0f + __expf(-r.x)));
            float e = __expf(clip_wk(fmaf(-wv.x, tr, k.x)));
            aa.x = fmaf(e, v.x, aa.x); bb.x += e;
        }
        {
            float eu  = __expf(clip_wk(uv.y + k.y));
            float wkv = fmaf(eu, v.y, aa.y) / (bb.y + eu);
            gv.y = f2tf32f(wkv / (1.0f + __expf(-r.y)));
            float e = __expf(clip_wk(fmaf(-wv.y, tr, k.y)));
            aa.y = fmaf(e, v.y, aa.y); bb.y += e;
        }
        {
            float eu  = __expf(clip_wk(uv.z + k.z));
            float wkv = fmaf(eu, v.z, aa.z) / (bb.z + eu);
            gv.z = f2tf32f(wkv / (1.0f + __expf(-r.z)));
            float e = __expf(clip_wk(fmaf(-wv.z, tr, k.z)));
            aa.z = fmaf(e, v.z, aa.z); bb.z += e;
        }
        {
            float eu  = __expf(clip_wk(uv.w + k.w));
            float wkv = fmaf(eu, v.w, aa.w) / (bb.w + eu);
            gv.w = f2tf32f(wkv / (1.0f + __expf(-r.w)));
            float e = __expf(clip_wk(fmaf(-wv.w, tr, k.w)));
            aa.w = fmaf(e, v.w, aa.w); bb.w += e;
        }
        *reinterpret_cast<float4*>(g_G + base + (size_t)i * C_) = gv;
    }
}

// ---------------------------------------------------------------------------
// Launch
// ---------------------------------------------------------------------------
extern "C" void kernel_launch(void* const* d_in, const int* in_sizes, int n_in,
                              void* d_out, int out_size)
{
    const float* x   = (const float*)d_in[0];
    const float* Wr  = (const float*)d_in[1];
    const float* br  = (const float*)d_in[2];
    const float* Wk  = (const float*)d_in[3];
    const float* bk  = (const float*)d_in[4];
    const float* Wv  = (const float*)d_in[5];
    const float* bv  = (const float*)d_in[6];
    const float* Wo  = (const float*)d_in[7];
    const float* bo  = (const float*)d_in[8];
    const float* td  = (const float*)d_in[9];
    const float* U   = (const float*)d_in[10];
    float*       out = (float*)d_out;

    // eps constants
    const double EPSd = exp(-1.0 / 12.0);
    const float  er  = (float)(EPSd / 2.0);
    const float  omr = (float)(1.0 - EPSd / 2.0);
    const float  ek  = (float)(EPSd + 0.3 * 1.0 / 11.0);
    const float  omk = (float)(1.0 - (EPSd + 0.3 * 1.0 / 11.0));
    const float  ev  = (float)EPSd;
    const float  omv = (float)(1.0 - EPSd);

    float *XR, *XK, *XV, *Rb, *Kb, *Vb, *Gb, *Wc;
    cudaGetSymbolAddress((void**)&XR, g_XR);
    cudaGetSymbolAddress((void**)&XK, g_XK);
    cudaGetSymbolAddress((void**)&XV, g_XV);
    cudaGetSymbolAddress((void**)&Rb, g_R);
    cudaGetSymbolAddress((void**)&Kb, g_K);
    cudaGetSymbolAddress((void**)&Vb, g_V);
    cudaGetSymbolAddress((void**)&Gb, g_G);
    cudaGetSymbolAddress((void**)&Wc, g_Wc);

    const int GEMM_SMEM = 4 * STAGE_SZ * (int)sizeof(float);  // 73728 B
    cudaFuncSetAttribute(gemm_tf32, cudaFuncAttributeMaxDynamicSharedMemorySize, GEMM_SMEM);

    // prep: interp + tf32 rounding, weight rounding
    interp_prep<<<(MTOT * C_ / 4 + 255) / 256, 256>>>(x, er, omr, ek, omk, ev, omv);
    weight_prep<<<dim3(C_ * C_ / 4 / 256, 4), 256>>>(Wr, Wk, Wv, Wo);

    dim3 ggrid(C_ / BN, MTOT / BM);   // (8, 64)

    // R/K/V projections
    gemm_tf32<<<ggrid, 256, GEMM_SMEM>>>(XR, Wc + 0 * (size_t)C_ * C_, br, Rb);
    gemm_tf32<<<ggrid, 256, GEMM_SMEM>>>(XK, Wc + 1 * (size_t)C_ * C_, bk, Kb);
    gemm_tf32<<<ggrid, 256, GEMM_SMEM>>>(XV, Wc + 2 * (size_t)C_ * C_, bv, Vb);

    // WKV (chunk-parallel cumsum)
    dim3 wgrid(NCHUNK, N_);
    wkv_partial<<<wgrid, 256>>>(td);
    wkv_scan<<<(N_ * C_ + 255) / 256, 256>>>();
    wkv_final<<<wgrid, 256>>>(td, U);

    // output projection
    gemm_tf32<<<ggrid, 256, GEMM_SMEM>>>(Gb, Wc + 3 * (size_t)C_ * C_, bo, out);
}

// round 13
// speedup vs baseline: 4.0004x; 1.0660x over previous
#include <cuda_runtime.h>
#include <math.h>
#include <stdint.h>

// ---------------------------------------------------------------------------
// Problem constants
// ---------------------------------------------------------------------------
#define N_      4
#define T_      2048
#define C_      1024        // = H*HS = attention dim = model dim
#define MTOT    (N_ * T_)   // 8192 rows for the GEMMs
#define NCHUNK  64
#define CS      (T_ / NCHUNK)   // 32 timesteps per chunk

// ---------------------------------------------------------------------------
// Scratch (allocation-free: __device__ globals)
// ---------------------------------------------------------------------------
__device__ float g_XR[MTOT * C_];   // tf32-rounded interpolated inputs
__device__ float g_XK[MTOT * C_];
__device__ float g_XV[MTOT * C_];
__device__ float g_R [MTOT * C_];
__device__ float g_K [MTOT * C_];
__device__ float g_V [MTOT * C_];
__device__ float g_G [MTOT * C_];   // tf32-rounded sigmoid(R)*WKV
__device__ float g_Wc[4 * C_ * C_]; // tf32-rounded Wr|Wk|Wv|Wo
__device__ float g_SA[N_ * NCHUNK * C_];
__device__ float g_SB[N_ * NCHUNK * C_];

// ---------------------------------------------------------------------------
// Helpers
// ---------------------------------------------------------------------------
__device__ __forceinline__ float clip_wk(float x) {
    return fminf(fmaxf(x, -20.0f), 10.0f);
}

__device__ __forceinline__ float f2tf32f(float f) {
    uint32_t u;
    asm("cvt.rna.tf32.f32 %0, %1;" : "=r"(u) : "f"(f));
    return __uint_as_float(u);
}

__device__ __forceinline__ void mma_tf32(float* d, const uint32_t* a, const uint32_t* b) {
    asm volatile(
        "mma.sync.aligned.m16n8k8.row.col.f32.tf32.tf32.f32 "
        "{%0,%1,%2,%3}, {%4,%5,%6,%7}, {%8,%9}, {%0,%1,%2,%3};\n"
        : "+f"(d[0]), "+f"(d[1]), "+f"(d[2]), "+f"(d[3])
        : "r"(a[0]), "r"(a[1]), "r"(a[2]), "r"(a[3]), "r"(b[0]), "r"(b[1]));
}

__device__ __forceinline__ void cp16(float* smem_dst, const float* gsrc) {
    uint32_t s = (uint32_t)__cvta_generic_to_shared(smem_dst);
    asm volatile("cp.async.cg.shared.global [%0], [%1], 16;\n" :: "r"(s), "l"(gsrc));
}
__device__ __forceinline__ void cp_commit() {
    asm volatile("cp.async.commit_group;\n");
}
__device__ __forceinline__ void cp_wait1() {
    asm volatile("cp.async.wait_group 1;\n");
}
__device__ __forceinline__ void cp_wait0() {
    asm volatile("cp.async.wait_group 0;\n");
}

// ---------------------------------------------------------------------------
// Prep 1: time interpolation + tf32 rounding (float4)
// ---------------------------------------------------------------------------
__global__ void interp_prep(const float* __restrict__ x,
                            float er, float omr,
                            float ek, float omk,
                            float ev, float omv)
{
    int idx4 = blockIdx.x * blockDim.x + threadIdx.x;
    if (idx4 >= MTOT * C_ / 4) return;
    size_t base = (size_t)idx4 * 4;
    int t = (int)((base / C_) % T_);

    float4 p  = make_float4(0.f, 0.f, 0.f, 0.f);
    float4 nx = make_float4(0.f, 0.f, 0.f, 0.f);
    if (t > 0)      p  = *reinterpret_cast<const float4*>(x + base - C_);
    if (t < T_ - 1) nx = *reinterpret_cast<const float4*>(x + base + C_);

    float4 r, k, v;
    r.x = f2tf32f(er * p.x + omr * nx.x);  r.y = f2tf32f(er * p.y + omr * nx.y);
    r.z = f2tf32f(er * p.z + omr * nx.z);  r.w = f2tf32f(er * p.w + omr * nx.w);
    k.x = f2tf32f(ek * p.x + omk * nx.x);  k.y = f2tf32f(ek * p.y + omk * nx.y);
    k.z = f2tf32f(ek * p.z + omk * nx.z);  k.w = f2tf32f(ek * p.w + omk * nx.w);
    v.x = f2tf32f(ev * p.x + omv * nx.x);  v.y = f2tf32f(ev * p.y + omv * nx.y);
    v.z = f2tf32f(ev * p.z + omv * nx.z);  v.w = f2tf32f(ev * p.w + omv * nx.w);

    *reinterpret_cast<float4*>(g_XR + base) = r;
    *reinterpret_cast<float4*>(g_XK + base) = k;
    *reinterpret_cast<float4*>(g_XV + base) = v;
}

// ---------------------------------------------------------------------------
// Prep 2: round weights to tf32.  blockIdx.y selects which weight.
// ---------------------------------------------------------------------------
__global__ void weight_prep(const float* __restrict__ w0, const float* __restrict__ w1,
                            const float* __restrict__ w2, const float* __restrict__ w3)
{
    int idx4 = blockIdx.x * blockDim.x + threadIdx.x;
    if (idx4 >= C_ * C_ / 4) return;
    const float* src = (blockIdx.y == 0) ? w0 : (blockIdx.y == 1) ? w1
                     : (blockIdx.y == 2) ? w2 : w3;
    size_t base = (size_t)idx4 * 4;
    float4 v = *reinterpret_cast<const float4*>(src + base);
    v.x = f2tf32f(v.x); v.y = f2tf32f(v.y); v.z = f2tf32f(v.z); v.w = f2tf32f(v.w);
    *reinterpret_cast<float4*>(g_Wc + (size_t)blockIdx.y * C_ * C_ + base) = v;
}

// ---------------------------------------------------------------------------
// TF32 tensor-core GEMM (NT), cp.async 3-stage ring, one barrier per K-tile.
//   C[m,j] = sum_k A[m,k]*W[j,k] + bias[j]
//   A, W already tf32-rounded.  128x128x32 tile, 8 warps of 64x32.
//   blockIdx.z selects among up to 3 fused (A, W, bias, Cout) problem sets.
// ---------------------------------------------------------------------------
#define BM 128
#define BN 128
#define BK 32
#define LDSS 36                  // 36 floats = 144B row stride: 16B aligned, conflict-free
#define STAGE_SZ (256 * LDSS)    // floats per stage (A half + B half)
#define BHALF (128 * LDSS)
#define NSTAGE 3
#define NKT (C_ / BK)            // 32
#define GEMM_SMEM (NSTAGE * STAGE_SZ * (int)sizeof(float))   // 110592 B

__global__ __launch_bounds__(256, 2)
void gemm_tf32(const float* __restrict__ A0, const float* __restrict__ A1,
               const float* __restrict__ A2,
               const float* __restrict__ Wc,
               const float* __restrict__ b0, const float* __restrict__ b1,
               const float* __restrict__ b2,
               float* __restrict__ C0, float* __restrict__ C1,
               float* __restrict__ C2,
               int wsel)
{
    extern __shared__ __align__(16) float sm[];   // [NSTAGE][STAGE_SZ]

    const int z = blockIdx.z;
    const float* A    = (z == 0) ? A0 : (z == 1) ? A1 : A2;
    const float* W    = Wc + (size_t)(wsel + z) * C_ * C_;
    const float* bias = (z == 0) ? b0 : (z == 1) ? b1 : b2;
    float*       Cout = (z == 0) ? C0 : (z == 1) ? C1 : C2;

    const int K  = C_;
    const int Nn = C_;

    const int tid    = threadIdx.x;
    const int bm     = blockIdx.y * BM;
    const int bn     = blockIdx.x * BN;
    const int warpId = tid >> 5;
    const int lane   = tid & 31;
    const int g      = lane >> 2;           // 0..7
    const int t4     = lane & 3;            // 0..3
    const int wr     = (warpId >> 2) * 64;  // warp row offset
    const int wc     = (warpId & 3) * 32;   // warp col offset

    const int lrow = tid >> 3;              // 0..31
    const int lcol = (tid & 7) * 4;         // 0,4,...,28

    const float* Abase = A + (size_t)(bm + lrow) * K + lcol;
    const float* Bbase = W + (size_t)(bn + lrow) * K + lcol;
    float* Asd = sm + lrow * LDSS + lcol;
    float* Bsd = sm + BHALF + lrow * LDSS + lcol;

    float acc[4][4][4];
    #pragma unroll
    for (int i = 0; i < 4; i++)
        #pragma unroll
        for (int j = 0; j < 4; j++)
            #pragma unroll
            for (int q = 0; q < 4; q++)
                acc[i][j][q] = 0.0f;

    auto load_stage = [&](int s, int kt) {
        const size_t ko = (size_t)kt * BK;
        #pragma unroll
        for (int i = 0; i < 4; i++) {
            cp16(Asd + s * STAGE_SZ + i * 32 * LDSS, Abase + ko + i * 32 * (size_t)K);
            cp16(Bsd + s * STAGE_SZ + i * 32 * LDSS, Bbase + ko + i * 32 * (size_t)K);
        }
        cp_commit();
    };

    // prologue: stages 0,1
    load_stage(0, 0);
    load_stage(1, 1);

    int cur = 0;   // stage holding tile kt
    for (int kt = 0; kt < NKT; kt++) {
        // arrive: tile kt's group complete (at most 1 newer group outstanding)
        if (kt + 1 < NKT) cp_wait1();
        else              cp_wait0();
        __syncthreads();   // single barrier: data visible AND stage (kt+2)%3 free

        // issue next prefetch AFTER the barrier (stage == stage read at kt-1)
        if (kt + 2 < NKT) {
            int nst = cur + 2; if (nst >= NSTAGE) nst -= NSTAGE;
            load_stage(nst, kt + 2);
        }

        const float* Ab = sm + cur * STAGE_SZ;
        const float* Bb = sm + cur * STAGE_SZ + BHALF;

        #pragma unroll
        for (int kk = 0; kk < 4; kk++) {
            const int kb = kk * 8;
            uint32_t afr[4][4];
            uint32_t bfr[4][2];
            #pragma unroll
            for (int mt = 0; mt < 4; mt++) {
                const int r0 = wr + mt * 16;
                afr[mt][0] = __float_as_uint(Ab[(r0 + g    ) * LDSS + kb + t4    ]);
                afr[mt][1] = __float_as_uint(Ab[(r0 + g + 8) * LDSS + kb + t4    ]);
                afr[mt][2] = __float_as_uint(Ab[(r0 + g    ) * LDSS + kb + t4 + 4]);
                afr[mt][3] = __float_as_uint(Ab[(r0 + g + 8) * LDSS + kb + t4 + 4]);
            }
            #pragma unroll
            for (int nt = 0; nt < 4; nt++) {
                const int c0 = wc + nt * 8;
                bfr[nt][0] = __float_as_uint(Bb[(c0 + g) * LDSS + kb + t4    ]);
                bfr[nt][1] = __float_as_uint(Bb[(c0 + g) * LDSS + kb + t4 + 4]);
            }
            #pragma unroll
            for (int mt = 0; mt < 4; mt++)
                #pragma unroll
                for (int nt = 0; nt < 4; nt++)
                    mma_tf32(acc[mt][nt], afr[mt], bfr[nt]);
        }

        cur++; if (cur >= NSTAGE) cur = 0;
    }

    // epilogue: bias + store
    #pragma unroll
    for (int mt = 0; mt < 4; mt++) {
        const int row = bm + wr + mt * 16 + g;
        #pragma unroll
        for (int nt = 0; nt < 4; nt++) {
            const int col = bn + wc + nt * 8 + t4 * 2;
            const float b0v = bias[col];
            const float b1v = bias[col + 1];
            float2 v0 = make_float2(acc[mt][nt][0] + b0v, acc[mt][nt][1] + b1v);
            float2 v1 = make_float2(acc[mt][nt][2] + b0v, acc[mt][nt][3] + b1v);
            *reinterpret_cast<float2*>(Cout + (size_t)row * Nn + col) = v0;
            *reinterpret_cast<float2*>(Cout + (size_t)(row + 8) * Nn + col) = v1;
        }
    }
}

// ---------------------------------------------------------------------------
// WKV recurrence (chunk-parallel cumsum, 3 passes).  256 threads, 4 ch/thread.
// ---------------------------------------------------------------------------
__global__ __launch_bounds__(256)
void wkv_partial(const float* __restrict__ td)
{
    const int c4    = threadIdx.x * 4;
    const int chunk = blockIdx.x;
    const int n     = blockIdx.y;

    float4 wv = *reinterpret_cast<const float4*>(td + c4);
    wv.x = fmaxf(wv.x, 0.f); wv.y = fmaxf(wv.y, 0.f);
    wv.z = fmaxf(wv.z, 0.f); wv.w = fmaxf(wv.w, 0.f);

    const int t0 = chunk * CS;
    const size_t base = ((size_t)n * T_ + t0) * C_ + c4;

    float4 sa = make_float4(0.f, 0.f, 0.f, 0.f);
    float4 sb = make_float4(0.f, 0.f, 0.f, 0.f);

    #pragma unroll 4
    for (int i = 0; i < CS; i++) {
        const float tr = (float)(T_ - 1 - (t0 + i));
        float4 k = *reinterpret_cast<const float4*>(g_K + base + (size_t)i * C_);
        float4 v = *reinterpret_cast<const float4*>(g_V + base + (size_t)i * C_);
        float ex = __expf(clip_wk(fmaf(-wv.x, tr, k.x)));
        float ey = __expf(clip_wk(fmaf(-wv.y, tr, k.y)));
        float ez = __expf(clip_wk(fmaf(-wv.z, tr, k.z)));
        float ew = __expf(clip_wk(fmaf(-wv.w, tr, k.w)));
        sa.x = fmaf(ex, v.x, sa.x); sb.x += ex;
        sa.y = fmaf(ey, v.y, sa.y); sb.y += ey;
        sa.z = fmaf(ez, v.z, sa.z); sb.z += ez;
        sa.w = fmaf(ew, v.w, sa.w); sb.w += ew;
    }
    size_t o = ((size_t)n * NCHUNK + chunk) * C_ + c4;
    *reinterpret_cast<float4*>(g_SA + o) = sa;
    *reinterpret_cast<float4*>(g_SB + o) = sb;
}

__global__ void wkv_scan()
{
    int idx = blockIdx.x * blockDim.x + threadIdx.x;   // over N_*C_
    if (idx >= N_ * C_) return;
    int n = idx / C_;
    int c = idx % C_;
    float ra = 0.0f, rb = 0.0f;
    for (int ch = 0; ch < NCHUNK; ch++) {
        size_t o = ((size_t)n * NCHUNK + ch) * C_ + c;
        float ta = g_SA[o], tb = g_SB[o];
        g_SA[o] = ra;                 // exclusive prefix
        g_SB[o] = rb;
        ra += ta;
        rb += tb;
    }
}

__global__ __launch_bounds__(256)
void wkv_final(const float* __restrict__ td, const float* __restrict__ U)
{
    const int c4    = threadIdx.x * 4;
    const int chunk = blockIdx.x;
    const int n     = blockIdx.y;

    float4 wv = *reinterpret_cast<const float4*>(td + c4);
    wv.x = fmaxf(wv.x, 0.f); wv.y = fmaxf(wv.y, 0.f);
    wv.z = fmaxf(wv.z, 0.f); wv.w = fmaxf(wv.w, 0.f);
    float4 uv = *reinterpret_cast<const float4*>(U + c4);

    size_t so = ((size_t)n * NCHUNK + chunk) * C_ + c4;
    float4 aa = *reinterpret_cast<const float4*>(g_SA + so);
    float4 bb = *reinterpret_cast<const float4*>(g_SB + so);

    const int t0 = chunk * CS;
    const size_t base = ((size_t)n * T_ + t0) * C_ + c4;

    #pragma unroll 2
    for (int i = 0; i < CS; i++) {
        const float tr = (float)(T_ - 1 - (t0 + i));
        float4 r = *reinterpret_cast<const float4*>(g_R + base + (size_t)i * C_);
        float4 k = *reinterpret_cast<const float4*>(g_K + base + (size_t)i * C_);
        float4 v = *reinterpret_cast<const float4*>(g_V + base + (size_t)i * C_);

        float4 gv;
        {
            float eu  = __expf(clip_wk(uv.x + k.x));
            float wkv = fmaf(eu, v.x, aa.x) / (bb.x + eu);
            gv.x = f2tf32f(wkv / (1.0f + __expf(-r.x)));
            float e = __expf(clip_wk(fmaf(-wv.x, tr, k.x)));
            aa.x = fmaf(e, v.x, aa.x); bb.x += e;
        }
        {
            float eu  = __expf(clip_wk(uv.y + k.y));
            float wkv = fmaf(eu, v.y, aa.y) / (bb.y + eu);
            gv.y = f2tf32f(wkv / (1.0f + __expf(-r.y)));
            float e = __expf(clip_wk(fmaf(-wv.y, tr, k.y)));
            aa.y = fmaf(e, v.y, aa.y); bb.y += e;
        }
        {
            float eu  = __expf(clip_wk(uv.z + k.z));
            float wkv = fmaf(eu, v.z, aa.z) / (bb.z + eu);
            gv.z = f2tf32f(wkv / (1.0f + __expf(-r.z)));
            float e = __expf(clip_wk(fmaf(-wv.z, tr, k.z)));
            aa.z = fmaf(e, v.z, aa.z); bb.z += e;
        }
        {
            float eu  = __expf(clip_wk(uv.w + k.w));
            float wkv = fmaf(eu, v.w, aa.w) / (bb.w + eu);
            gv.w = f2tf32f(wkv / (1.0f + __expf(-r.w)));
            float e = __expf(clip_wk(fmaf(-wv.w, tr, k.w)));
            aa.w = fmaf(e, v.w, aa.w); bb.w += e;
        }
        *reinterpret_cast<float4*>(g_G + base + (size_t)i * C_) = gv;
    }
}

// ---------------------------------------------------------------------------
// Launch
// ---------------------------------------------------------------------------
extern "C" void kernel_launch(void* const* d_in, const int* in_sizes, int n_in,
                              void* d_out, int out_size)
{
    const float* x   = (const float*)d_in[0];
    const float* Wr  = (const float*)d_in[1];
    const float* br  = (const float*)d_in[2];
    const float* Wk  = (const float*)d_in[3];
    const float* bk  = (const float*)d_in[4];
    const float* Wv  = (const float*)d_in[5];
    const float* bv  = (const float*)d_in[6];
    const float* Wo  = (const float*)d_in[7];
    const float* bo  = (const float*)d_in[8];
    const float* td  = (const float*)d_in[9];
    const float* U   = (const float*)d_in[10];
    float*       out = (float*)d_out;

    // eps constants
    const double EPSd = exp(-1.0 / 12.0);
    const float  er  = (float)(EPSd / 2.0);
    const float  omr = (float)(1.0 - EPSd / 2.0);
    const float  ek  = (float)(EPSd + 0.3 * 1.0 / 11.0);
    const float  omk = (float)(1.0 - (EPSd + 0.3 * 1.0 / 11.0));
    const float  ev  = (float)EPSd;
    const float  omv = (float)(1.0 - EPSd);

    float *XR, *XK, *XV, *Rb, *Kb, *Vb, *Gb, *Wc;
    cudaGetSymbolAddress((void**)&XR, g_XR);
    cudaGetSymbolAddress((void**)&XK, g_XK);
    cudaGetSymbolAddress((void**)&XV, g_XV);
    cudaGetSymbolAddress((void**)&Rb, g_R);
    cudaGetSymbolAddress((void**)&Kb, g_K);
    cudaGetSymbolAddress((void**)&Vb, g_V);
    cudaGetSymbolAddress((void**)&Gb, g_G);
    cudaGetSymbolAddress((void**)&Wc, g_Wc);

    cudaFuncSetAttribute(gemm_tf32, cudaFuncAttributeMaxDynamicSharedMemorySize, GEMM_SMEM);

    // prep: interp + tf32 rounding, weight rounding
    interp_prep<<<(MTOT * C_ / 4 + 255) / 256, 256>>>(x, er, omr, ek, omk, ev, omv);
    weight_prep<<<dim3(C_ * C_ / 4 / 256, 4), 256>>>(Wr, Wk, Wv, Wo);

    // R/K/V projections fused into one launch (z = 0,1,2)
    dim3 rkv_grid(C_ / BN, MTOT / BM, 3);   // (8, 64, 3)
    gemm_tf32<<<rkv_grid, 256, GEMM_SMEM>>>(XR, XK, XV, Wc, br, bk, bv,
                                            Rb, Kb, Vb, /*wsel=*/0);

    // WKV (chunk-parallel cumsum)
    dim3 wgrid(NCHUNK, N_);
    wkv_partial<<<wgrid, 256>>>(td);
    wkv_scan<<<(N_ * C_ + 255) / 256, 256>>>();
    wkv_final<<<wgrid, 256>>>(td, U);

    // output projection (single z)
    dim3 o_grid(C_ / BN, MTOT / BM, 1);
    gemm_tf32<<<o_grid, 256, GEMM_SMEM>>>(Gb, Gb, Gb, Wc, bo, bo, bo,
                                          out, out, out, /*wsel=*/3);
}